// round 9
// baseline (speedup 1.0000x reference)
#include <cuda_runtime.h>
#include <cstdint>
#include <cstddef>

// ============================================================================
// MultiRegionRNN on GB300 — fp32, one kernel launch per timestep.
// Round 8: batch-split partition + 3-stage pipeline, 1 barrier/tile.
//   - per-CTA tile: m1 32b x 16c x K1536 (2 bgroups), pmd 16b x 48c x K1024
//     (4 bgroups), s1 16b x 96c x K512 (4 bgroups). 132 CTAs, all exactly
//     786K MACs -> 768 FFMA2 per warp. R L2 traffic cut 2-4x (b-split is
//     embarrassingly parallel: no new cross-CTA reductions).
//   - 3 smem buffers, cp.async prefetch distance 2, one __syncthreads/tile.
//   - uniform warp map (512 thr): kwid=w&7 (16-float k-window), cpart=w>>3;
//     lane: rg=lane&3 (rows rg+4i), cg=lane>>2 (8 col slots).
// ============================================================================

#define NBLK 132
#define KT 128
#define RSP 132                 // R tile row stride (floats)
#define WSP 132                 // W tile row stride (floats)
#define RJ2 36                  // reduction row stride (floats) -> 4j+b banks

typedef unsigned long long u64t;

__device__ float g_XP[499u * 64u * 1024u];   // hoisted input projections
__device__ float g_R[2u * 64u * 1536u];      // double-buffered rates [buf][b][k]
__device__ float g_X[1536u * 64u];           // pre-activation state [j][b]

#define FMA_F32X2(d, a, b) \
    asm("fma.rn.f32x2 %0, %1, %2, %0;" : "+l"(d) : "l"(a), "l"(b))

// ---------------------------------------------------------------------------
__global__ void init_kernel() {
    int idx = blockIdx.x * blockDim.x + threadIdx.x;
    if (idx < 64 * 1536) {
        g_X[idx] = 0.f;
        g_R[idx] = 0.f;   // buffer 0: step 0 reads zeros = tanh(0) rates
    }
}

// ---------------------------------------------------------------------------
// XP[t][b][jj], jj in [0,1024): jj<512 -> pmd input proj, else s1.
// ---------------------------------------------------------------------------
__global__ void __launch_bounds__(256) xp_kernel(
    const float* __restrict__ X,
    const float* __restrict__ W_in_pmd,
    const float* __restrict__ W_in_s1,
    const float* __restrict__ b_pmd,
    const float* __restrict__ b_s1)
{
    extern __shared__ float sm[];
    float* Ws  = sm;               // [128][101]
    float* Xst = sm + 128 * 101;   // [100][68]

    const int t   = blockIdx.y;
    const int jb  = blockIdx.x;
    const int tid = threadIdx.x;

    for (int idx = tid; idx < 128 * 100; idx += 256) {
        int j = idx / 100, d = idx - j * 100;
        int jg = jb * 128 + j;
        float v = (jg < 512) ? W_in_pmd[jg * 100 + d] : W_in_s1[(jg - 512) * 100 + d];
        Ws[j * 101 + d] = v;
    }
    const float* Xt = X + (size_t)(t + 1) * 6400;
    for (int idx = tid; idx < 6400; idx += 256) {
        int b = idx / 100, d = idx - b * 100;
        Xst[d * 68 + b] = Xt[idx];
    }
    __syncthreads();

    const int j  = tid & 127;
    const int bh = tid >> 7;
    const int jg = jb * 128 + j;

    float acc[32];
#pragma unroll
    for (int i = 0; i < 32; i++) acc[i] = 0.f;

    for (int d = 0; d < 100; d++) {
        float w = Ws[j * 101 + d];
        const float4* xr = (const float4*)&Xst[d * 68 + bh * 32];
#pragma unroll
        for (int i = 0; i < 8; i++) {
            float4 xv = xr[i];
            acc[4 * i + 0] += w * xv.x;
            acc[4 * i + 1] += w * xv.y;
            acc[4 * i + 2] += w * xv.z;
            acc[4 * i + 3] += w * xv.w;
        }
    }
    float bias = (jg < 512) ? b_pmd[jg] : b_s1[jg - 512];
#pragma unroll
    for (int i = 0; i < 32; i++) {
        int b = bh * 32 + i;
        g_XP[(size_t)(t * 64 + b) * 1024 + jg] = acc[i] + bias;
    }
}

// ---------------------------------------------------------------------------
struct RnnParams {
    const float* Wrec_m1;
    const float* Wrec_pmd;
    const float* Wrec_s1;
    const float* b_m1;
    const float* b_pmd;
    const float* b_s1;
    const float* Wpmd_m1;
    const float* Ws1_m1;
    const float* Wm1_pmd;
    const float* Wout;
    float* out;
};

__device__ __forceinline__ void cp16(unsigned dst, const void* src) {
    asm volatile("cp.async.cg.shared.global [%0], [%1], 16;\n" :: "r"(dst), "l"(src));
}
__device__ __forceinline__ void cp_commit() {
    asm volatile("cp.async.commit_group;\n");
}
template <int N>
__device__ __forceinline__ void cp_wait() {
    asm volatile("cp.async.wait_group %0;\n" :: "n"(N));
}
__device__ __forceinline__ unsigned smaddr(const void* p) {
    return (unsigned)__cvta_generic_to_shared(p);
}

// Source row pointer for weight tile; k0 = region-local column offset
template <int REGION>
__device__ __forceinline__ const float* wrow(const RnnParams& P, int jg, int k0) {
    if (REGION == 0) {
        if (k0 < 512)  return P.Wrec_m1 + jg * 512 + k0;
        if (k0 < 1024) return P.Wpmd_m1 + jg * 512 + (k0 - 512);
        return P.Ws1_m1 + jg * 512 + (k0 - 1024);
    } else if (REGION == 1) {
        int jp = jg - 512;
        if (k0 < 512) return P.Wm1_pmd + jp * 512 + k0;
        return P.Wrec_pmd + jp * 512 + (k0 - 512);
    } else {
        return P.Wrec_s1 + (jg - 1024) * 512 + k0;
    }
}

template <int ROWS, int NC, int K, int REGION, int CT>
__device__ __forceinline__ void step_region(const RnnParams& P, int s, int colbase,
                                            int nc, int row0, float* sm, int cta)
{
    constexpr int RT     = ROWS / 4;            // rows per lane
    constexpr int NT     = K / KT;              // k tiles
    constexpr int COLSPP = NC / 2;              // cols per warp-part
    constexpr int LOGR   = (ROWS == 32) ? 5 : 4;
    constexpr int KBASE  = (REGION == 2) ? 1024 : 0;

    float* Rb = sm;                       // 3 x ROWS x RSP
    float* Wb = sm + 3 * ROWS * RSP;      // 3 x NC x WSP
    float* red = sm;                      // overlay after mainloop

    const int tid  = threadIdx.x;
    const int w    = tid >> 5;
    const int lane = tid & 31;
    const int rg   = lane & 3;            // row group: rows rg + 4i
    const int cg   = lane >> 2;           // col slot 0..7
    const int kwid = w & 7;               // 16-float k-window
    const int cpart = w >> 3;             // 0/1
    const int jbase = cpart * COLSPP;

    const int rb   = s & 1;
    const int wbuf = rb ^ 1;
    const float* Rg = g_R + (size_t)rb * (64 * 1536) + KBASE;

    // ---- stage tiles 0 and 1 ----
#pragma unroll
    for (int pre = 0; pre < 2; pre++) {
        float* Rt = Rb + pre * ROWS * RSP;
        float* Wt = Wb + pre * NC * WSP;
        const int kg = pre * KT;
        for (int c = tid; c < ROWS * 32; c += 512) {
            int b = c >> 5, q = c & 31;
            cp16(smaddr(Rt + b * RSP + q * 4), Rg + (row0 + b) * 1536 + kg + q * 4);
        }
        for (int c = tid; c < NC * 32; c += 512) {
            int j = c >> 5, q = c & 31;
            int jj = (j < nc) ? j : 0;
            cp16(smaddr(Wt + j * WSP + q * 4), wrow<REGION>(P, colbase + jj, kg) + q * 4);
        }
        cp_commit();
    }

    // ---- previous step's readout (data consistent at launch boundary) ----
    if (s > 0 && w < 5) {
        int p = cta * 5 + w;
        if (p < 640) {
            int b = p / 10, o = p - b * 10;
            const float* Rm = g_R + (size_t)rb * (64 * 1536) + b * 1536;
            const float* Wo = P.Wout + o * 512;
            float sum = 0.f;
            for (int k = lane; k < 512; k += 32) sum += Rm[k] * Wo[k];
#pragma unroll
            for (int off = 16; off; off >>= 1)
                sum += __shfl_down_sync(0xffffffffu, sum, off);
            if (lane == 0) P.out[(size_t)((s - 1) * 64 + b) * 10 + o] = sum;
        }
    }

    // ---- mainloop: 3 buffers, prefetch distance 2, ONE sync per tile ----
    u64t acc2[RT * CT];
#pragma unroll
    for (int i = 0; i < RT * CT; i++) acc2[i] = 0ull;

    for (int kt = 0; kt < NT; kt++) {
        if (kt + 1 < NT) cp_wait<1>(); else cp_wait<0>();
        __syncthreads();   // tile kt visible; buffer (kt+2)%3 free (kt-1 consumed)

        if (kt + 2 < NT) {
            const int nb = (kt + 2) % 3;
            const int kg = (kt + 2) * KT;
            float* Rt = Rb + nb * ROWS * RSP;
            float* Wt = Wb + nb * NC * WSP;
            for (int c = tid; c < ROWS * 32; c += 512) {
                int b = c >> 5, q = c & 31;
                cp16(smaddr(Rt + b * RSP + q * 4), Rg + (row0 + b) * 1536 + kg + q * 4);
            }
            for (int c = tid; c < NC * 32; c += 512) {
                int j = c >> 5, q = c & 31;
                int jj = (j < nc) ? j : 0;
                cp16(smaddr(Wt + j * WSP + q * 4),
                     wrow<REGION>(P, colbase + jj, kg) + q * 4);
            }
            cp_commit();
        }

        const float* Rt = Rb + (kt % 3) * ROWS * RSP;
        const float* Wt = Wb + (kt % 3) * NC * WSP;
#pragma unroll
        for (int q = 0; q < 4; q++) {
            const int ko = kwid * 16 + (q << 2);
            ulonglong2 rv[RT];
#pragma unroll
            for (int i = 0; i < RT; i++)
                rv[i] = *(const ulonglong2*)&Rt[(rg + 4 * i) * RSP + ko];
            ulonglong2 wv[CT];
#pragma unroll
            for (int t = 0; t < CT; t++)
                wv[t] = *(const ulonglong2*)&Wt[(jbase + cg + 8 * t) * WSP + ko];
#pragma unroll
            for (int i = 0; i < RT; i++) {
#pragma unroll
                for (int t = 0; t < CT; t++) {
                    FMA_F32X2(acc2[i * CT + t], rv[i].x, wv[t].x);
                    FMA_F32X2(acc2[i * CT + t], rv[i].y, wv[t].y);
                }
            }
        }
    }
    __syncthreads();   // all warps done with tile buffers before red overlay

    // ---- cross-warp k-partial reduction (8 partials, overlay smem) ----
#pragma unroll
    for (int t = 0; t < CT; t++) {
        int j = jbase + cg + 8 * t;
#pragma unroll
        for (int i = 0; i < RT; i++) {
            int b = rg + 4 * i;
            float2 p2 = *(float2*)&acc2[i * CT + t];
            red[(kwid * NC + j) * RJ2 + b] = p2.x + p2.y;
        }
    }
    __syncthreads();

    // ---- epilogue: reduce 8 partials, leaky update + tanh, publish ----
    const float A = 0.1f, OMA = 0.9f;
    const float* bias = (REGION == 0) ? P.b_m1 + colbase
                      : (REGION == 1) ? P.b_pmd + (colbase - 512)
                                      : P.b_s1 + (colbase - 1024);
    float* Rw = g_R + (size_t)wbuf * (64 * 1536);
    const int nout = ROWS * nc;
    for (int o = tid; o < nout; o += 512) {
        int j = o >> LOGR, b = o & (ROWS - 1);
        float sum = 0.f;
#pragma unroll
        for (int kw = 0; kw < 8; kw++) sum += red[(kw * NC + j) * RJ2 + b];
        int jg = colbase + j;
        int bg = row0 + b;
        float v = sum + bias[j];
        if (REGION != 0) v += g_XP[(size_t)(s * 64 + bg) * 1024 + (jg - 512)];
        float x = OMA * g_X[jg * 64 + bg] + A * v;
        g_X[jg * 64 + bg] = x;
        Rw[bg * 1536 + jg] = tanhf(x);
    }
}

__global__ void __launch_bounds__(512, 1) step_kernel(RnnParams P, int s) {
    extern __shared__ float sm[];
    const int cta = blockIdx.x;
    if (cta < 64) {
        // m1: 2 bgroups x 32 colgroups, 32 rows x 16 cols x K1536
        int bg = cta >> 5, cgi = cta & 31;
        step_region<32, 16, 1536, 0, 1>(P, s, cgi * 16, 16, bg * 32, sm, cta);
    } else if (cta < 108) {
        // pmd: 4 bgroups x 11 colgroups, 16 rows x 48 cols x K1024
        int i = cta - 64, bg = i / 11, cgi = i % 11;
        step_region<16, 48, 1024, 1, 3>(P, s, 512 + cgi * 48,
                                        (cgi < 10) ? 48 : 32, bg * 16, sm, cta);
    } else {
        // s1: 4 bgroups x 6 colgroups, 16 rows x 96 cols x K512
        int i = cta - 108, bg = i / 6, cgi = i % 6;
        step_region<16, 96, 512, 2, 6>(P, s, 1024 + cgi * 96,
                                       (cgi < 5) ? 96 : 32, bg * 16, sm, cta);
    }
}

// --------------------------------------------------------------------------
// Final readout: out[498] from rate buffer 1 (written by step s=498).
// --------------------------------------------------------------------------
__global__ void __launch_bounds__(256) readout_final(const float* __restrict__ Wout,
                                                     float* __restrict__ out)
{
    const int w = threadIdx.x >> 5;
    const int l = threadIdx.x & 31;
    const int p = blockIdx.x * 8 + w;
    if (p >= 640) return;
    int b = p / 10, o = p - b * 10;
    const float* Rm = g_R + (size_t)1 * (64 * 1536) + b * 1536;
    const float* Wo = Wout + o * 512;
    float sum = 0.f;
    for (int k = l; k < 512; k += 32) sum += Rm[k] * Wo[k];
#pragma unroll
    for (int off = 16; off; off >>= 1)
        sum += __shfl_down_sync(0xffffffffu, sum, off);
    if (l == 0) out[(size_t)(498 * 64 + b) * 10 + o] = sum;
}

// ---------------------------------------------------------------------------
static const int XP_SMEM  = (128 * 101 + 100 * 68) * 4;          // 78912 B
static const int RNN_SMEM = 3 * (16 + 96) * WSP * 4;             // 177408 B (s1 max)

extern "C" void kernel_launch(void* const* d_in, const int* in_sizes, int n_in,
                              void* d_out, int out_size)
{
    const float* X        = (const float*)d_in[0];
    const float* Wrec_m1  = (const float*)d_in[1];
    const float* Wrec_pmd = (const float*)d_in[2];
    const float* Wrec_s1  = (const float*)d_in[3];
    const float* b_m1     = (const float*)d_in[4];
    const float* b_pmd    = (const float*)d_in[5];
    const float* b_s1     = (const float*)d_in[6];
    const float* Wpmd_m1  = (const float*)d_in[7];
    const float* Ws1_m1   = (const float*)d_in[8];
    const float* Wm1_pmd  = (const float*)d_in[9];
    const float* W_in_pmd = (const float*)d_in[10];
    const float* W_in_s1  = (const float*)d_in[11];
    const float* Wout     = (const float*)d_in[12];
    float* out = (float*)d_out;

    cudaFuncSetAttribute(xp_kernel,   cudaFuncAttributeMaxDynamicSharedMemorySize, XP_SMEM);
    cudaFuncSetAttribute(step_kernel, cudaFuncAttributeMaxDynamicSharedMemorySize, RNN_SMEM);

    RnnParams P;
    P.Wrec_m1 = Wrec_m1; P.Wrec_pmd = Wrec_pmd; P.Wrec_s1 = Wrec_s1;
    P.b_m1 = b_m1; P.b_pmd = b_pmd; P.b_s1 = b_s1;
    P.Wpmd_m1 = Wpmd_m1; P.Ws1_m1 = Ws1_m1; P.Wm1_pmd = Wm1_pmd;
    P.Wout = Wout; P.out = out;

    init_kernel<<<(64 * 1536 + 255) / 256, 256>>>();
    xp_kernel<<<dim3(8, 499), 256, XP_SMEM>>>(X, W_in_pmd, W_in_s1, b_pmd, b_s1);
    for (int s = 0; s < 499; s++)
        step_kernel<<<NBLK, 512, RNN_SMEM>>>(P, s);
    readout_final<<<80, 256>>>(Wout, out);
}